// round 6
// baseline (speedup 1.0000x reference)
#include <cuda_runtime.h>
#include <math.h>

// ---------------- problem constants ----------------
#define Bz   16
#define Nn   1024
#define Hh   64
#define NB   64
#define NT   16          // Nn / NB
#define ETA_ 0.01f

// output layout (tuple order, flattened)
#define SP_OFF    0
#define DEC_OFF   32
#define GAMMA_OFF (32 + Bz*Nn*Hh)            // 1048608
#define PROP_OFF  (GAMMA_OFF + Bz*Nn)        // 1064992

// ---------------- device scratch (static, no runtime alloc) ----------------
__device__ __align__(16) float2 g_A[Bz][Nn][Nn];   // working matrices -> inverses (134 MB)
__device__ __align__(16) float2 g_F[Bz][Nn][NB];   // column-block snapshot (8.4 MB)
__device__ float g_Hs[Nn][Nn];                     // 0.5*(H+H^T) (4 MB)
__device__ float g_cell[Bz][Hh];
__device__ float g_omega[Bz][Nn];
__device__ float g_wre[Bz];

// ---------------- complex helpers ----------------
template<bool SUB>
__device__ __forceinline__ void cfma(float2& c, const float2 a, const float2 b) {
    if (SUB) {
        c.x = fmaf(-a.x, b.x, c.x); c.x = fmaf( a.y, b.y, c.x);
        c.y = fmaf(-a.x, b.y, c.y); c.y = fmaf(-a.y, b.x, c.y);
    } else {
        c.x = fmaf( a.x, b.x, c.x); c.x = fmaf(-a.y, b.y, c.x);
        c.y = fmaf( a.x, b.y, c.y); c.y = fmaf( a.y, b.x, c.y);
    }
}

// 64x64x64 complex tile GEMM: acc (4x4 per thread) +/-= Ls[r][k] * Rs[k][c]
template<bool SUB>
__device__ __forceinline__ void tile_cgemm(const float2 (*Ls)[64], const float2 (*Rs)[64],
                                           float2 (*acc)[4], int r0, int c0) {
#pragma unroll 4
    for (int kk = 0; kk < 64; kk++) {
        float2 a0 = Ls[r0+0][kk], a1 = Ls[r0+1][kk], a2 = Ls[r0+2][kk], a3 = Ls[r0+3][kk];
        float4 q0 = *(const float4*)&Rs[kk][c0];
        float4 q1 = *(const float4*)&Rs[kk][c0+2];
        float2 b0 = make_float2(q0.x, q0.y), b1 = make_float2(q0.z, q0.w);
        float2 b2 = make_float2(q1.x, q1.y), b3 = make_float2(q1.z, q1.w);
        cfma<SUB>(acc[0][0], a0, b0); cfma<SUB>(acc[0][1], a0, b1);
        cfma<SUB>(acc[0][2], a0, b2); cfma<SUB>(acc[0][3], a0, b3);
        cfma<SUB>(acc[1][0], a1, b0); cfma<SUB>(acc[1][1], a1, b1);
        cfma<SUB>(acc[1][2], a1, b2); cfma<SUB>(acc[1][3], a1, b3);
        cfma<SUB>(acc[2][0], a2, b0); cfma<SUB>(acc[2][1], a2, b1);
        cfma<SUB>(acc[2][2], a2, b2); cfma<SUB>(acc[2][3], a2, b3);
        cfma<SUB>(acc[3][0], a3, b0); cfma<SUB>(acc[3][1], a3, b1);
        cfma<SUB>(acc[3][2], a3, b2); cfma<SUB>(acc[3][3], a3, b3);
    }
}

// ---------------- small/fused kernels ----------------

// cell[b][h] = mean_n gene[b][n][h]
__global__ void k_cell(const float* __restrict__ gene) {
    __shared__ float part[256];
    int b = blockIdx.x, t = threadIdx.x;
    int h = t & 63, chunk = t >> 6;
    const float* base = gene + ((size_t)b*Nn + chunk*256)*Hh + h;
    float s = 0.f;
    for (int n = 0; n < 256; n++) s += base[(size_t)n*Hh];
    part[t] = s;
    __syncthreads();
    if (t < 64)
        g_cell[b][t] = (part[t] + part[t+64] + part[t+128] + part[t+192]) * (1.0f/1024.0f);
}

// per-token MLPs: env->gamma, decohered, omega (one warp per (b,n))
__global__ __launch_bounds__(256) void k_mlp(
    const float* __restrict__ gene, const float* __restrict__ coh,
    const float* __restrict__ gb,
    const float* __restrict__ ew1, const float* __restrict__ eb1,
    const float* __restrict__ ew2, const float* __restrict__ eb2,
    const float* __restrict__ ow1, const float* __restrict__ ob1,
    const float* __restrict__ ow2, const float* __restrict__ ob2,
    float* __restrict__ out)
{
    __shared__ float swe[64][32], swo[64][32];
    __shared__ float sg[8][64];
    __shared__ float sw2e[32], sw2o[32];
    int t = threadIdx.x;
#pragma unroll
    for (int s = 0; s < 8; s++) {
        int e = t + 256*s;
        swe[e>>5][e&31] = ew1[e];
        swo[e>>5][e&31] = ow1[e];
    }
    if (t < 32) { sw2e[t] = ew2[t]; sw2o[t] = ow2[t]; }
    __syncthreads();

    int w = t >> 5, lane = t & 31;
    int row = blockIdx.x * 8 + w;           // b*N + n
    int b = row >> 10, n = row & (Nn-1);

    const float* grow = gene + (size_t)row*Hh;
    sg[w][lane]    = grow[lane];
    sg[w][lane+32] = grow[lane+32];
    __syncwarp();

    float ae = eb1[lane], ao = ob1[lane];
#pragma unroll
    for (int h = 0; h < 64; h++) {
        float g = sg[w][h];
        ae = fmaf(g, swe[h][lane], ae);
        ao = fmaf(g, swo[h][lane], ao);
    }
    float h1 = ae / (1.0f + expf(-ae));   // silu
    float o1 = ao / (1.0f + expf(-ao));
    float ve = h1 * sw2e[lane];
    float vo = o1 * sw2o[lane];
    float cs = sg[w][lane] + sg[w][lane+32];
#pragma unroll
    for (int off = 16; off; off >>= 1) {
        ve += __shfl_xor_sync(0xffffffffu, ve, off);
        vo += __shfl_xor_sync(0xffffffffu, vo, off);
        cs += __shfl_xor_sync(0xffffffffu, cs, off);
    }
    float env   = 1.0f / (1.0f + expf(-(ve + eb2[0])));
    float omega = vo + ob2[0];
    float gamma = (1.0f / (1.0f + expf(-gb[n]))) * (1.0f + env);
    float classical = cs * (1.0f/64.0f);

    if (lane == 0) {
        out[GAMMA_OFF + row] = gamma;
        g_omega[b][n] = omega;
    }
    float om1 = 1.0f - gamma;
    const float* crow = coh + (size_t)row*Hh;
    float* drow = out + DEC_OFF + (size_t)row*Hh;
    drow[lane]    = om1*crow[lane]    + gamma*classical;
    drow[lane+32] = om1*crow[lane+32] + gamma*classical;
}

// deterministic omega mean per batch
__global__ void k_omred() {
    __shared__ float s[256];
    int b = blockIdx.x, t = threadIdx.x;
    s[t] = g_omega[b][t] + g_omega[b][t+256] + g_omega[b][t+512] + g_omega[b][t+768];
    __syncthreads();
    for (int off = 128; off; off >>= 1) { if (t < off) s[t] += s[t+off]; __syncthreads(); }
    if (t == 0) g_wre[b] = s[0] * (1.0f/1024.0f);
}

// state_probs (16x2)
__global__ void k_probs(const float* __restrict__ emb, float* __restrict__ out) {
    int t = threadIdx.x;
    if (t >= 16) return;
    float nc = 0.f, d0 = 0.f, d1 = 0.f, n0 = 0.f, n1 = 0.f;
    for (int d = 0; d < 64; d++) {
        float c = g_cell[t][d];
        float e0 = emb[d], e1 = emb[64 + d];
        nc = fmaf(c, c, nc); d0 = fmaf(c, e0, d0); d1 = fmaf(c, e1, d1);
        n0 = fmaf(e0, e0, n0); n1 = fmaf(e1, e1, n1);
    }
    float ic = 1.0f / fmaxf(sqrtf(nc), 1e-12f);
    float l0 = d0 * ic / fmaxf(sqrtf(n0), 1e-12f) * 10.0f;
    float l1 = d1 * ic / fmaxf(sqrtf(n1), 1e-12f) * 10.0f;
    float m = fmaxf(l0, l1);
    float p0 = expf(l0 - m), p1 = expf(l1 - m);
    float is = 1.0f / (p0 + p1);
    out[SP_OFF + t*2 + 0] = p0 * is;
    out[SP_OFF + t*2 + 1] = p1 * is;
}

// Hs = 0.5*(H + H^T)  (tiled transpose)
__global__ void k_sym(const float* __restrict__ Hm) {
    __shared__ float tile[32][33];
    int bx = blockIdx.x, by = blockIdx.y;
    int tx = threadIdx.x, ty = threadIdx.y;
#pragma unroll
    for (int s = 0; s < 32; s += 8)
        tile[ty+s][tx] = Hm[(size_t)(bx*32 + ty + s)*Nn + by*32 + tx];
    __syncthreads();
#pragma unroll
    for (int s = 0; s < 32; s += 8) {
        int i = by*32 + ty + s, j = bx*32 + tx;
        g_Hs[i][j] = 0.5f * (Hm[(size_t)i*Nn + j] + tile[tx][ty+s]);
    }
}

// A_b = (w_b + i*eta) I - Hs
__global__ void k_build() {
    int i = blockIdx.x, b = blockIdx.y, t = threadIdx.x;
    float wre = g_wre[b];
#pragma unroll
    for (int s = 0; s < 4; s++) {
        int j = t + 256*s;
        float re = ((i == j) ? wre : 0.0f) - g_Hs[i][j];
        g_A[b][i][j] = make_float2(re, (i == j) ? ETA_ : 0.0f);
    }
}

// ---------------- blocked Gauss-Jordan (no pivoting; Im>=eta*I guarantees pivots) ----------------

// invert 64x64 diagonal block in place
__global__ __launch_bounds__(256) void k_diag(int kb) {
    __shared__ float2 M[64][64];
    int b = blockIdx.x, t = threadIdx.x;
    int kbase = kb * NB;
#pragma unroll
    for (int s = 0; s < 16; s++) {
        int e = t + 256*s; int r = e >> 6, c = e & 63;
        M[r][c] = g_A[b][kbase + r][kbase + c];
    }
    __syncthreads();
    int jj = t & 63, i0 = t >> 6;
    for (int k = 0; k < 64; k++) {
        float2 p = M[k][k];
        float id = 1.0f / (p.x*p.x + p.y*p.y);
        float2 pinv = make_float2(p.x*id, -p.y*id);
        float2 rk = M[k][jj];
        float2 f[16];
#pragma unroll
        for (int m = 0; m < 16; m++) f[m] = M[i0 + 4*m][k];
        __syncthreads();
        float2 nrk;
        if (jj == k) nrk = pinv;
        else nrk = make_float2(rk.x*pinv.x - rk.y*pinv.y, rk.x*pinv.y + rk.y*pinv.x);
#pragma unroll
        for (int m = 0; m < 16; m++) {
            int i = i0 + 4*m;
            if (i == k) {
                M[k][jj] = nrk;
            } else if (jj == k) {
                M[i][k] = make_float2(-(f[m].x*pinv.x - f[m].y*pinv.y),
                                      -(f[m].x*pinv.y + f[m].y*pinv.x));
            } else {
                float2 v = M[i][jj];
                v.x -= f[m].x*nrk.x - f[m].y*nrk.y;
                v.y -= f[m].x*nrk.y + f[m].y*nrk.x;
                M[i][jj] = v;
            }
        }
        __syncthreads();
    }
#pragma unroll
    for (int s = 0; s < 16; s++) {
        int e = t + 256*s; int r = e >> 6, c = e & 63;
        g_A[b][kbase + r][kbase + c] = M[r][c];
    }
}

// row-block scale: A[k, jt] <- P @ A[k, jt]   (jt != kb)
__global__ __launch_bounds__(256) void k_rowscale(int kb) {
    int jt = blockIdx.x, b = blockIdx.y;
    if (jt == kb) return;
    __shared__ __align__(16) float2 Ls[64][64];
    __shared__ __align__(16) float2 Rs[64][64];
    int t = threadIdx.x;
    int kbase = kb * NB, jbase = jt * NB;
#pragma unroll
    for (int s = 0; s < 16; s++) {
        int e = t + 256*s; int r = e >> 6, c = e & 63;
        Ls[r][c] = g_A[b][kbase + r][kbase + c];   // P
        Rs[r][c] = g_A[b][kbase + r][jbase + c];   // old row tile
    }
    __syncthreads();
    int tx = t & 15, ty = t >> 4, r0 = ty*4, c0 = tx*4;
    float2 acc[4][4];
#pragma unroll
    for (int d = 0; d < 4; d++)
#pragma unroll
        for (int e2 = 0; e2 < 4; e2++) acc[d][e2] = make_float2(0.f, 0.f);
    tile_cgemm<false>(Ls, Rs, acc, r0, c0);
#pragma unroll
    for (int d = 0; d < 4; d++) {
        *(float4*)&g_A[b][kbase + r0 + d][jbase + c0]     =
            make_float4(acc[d][0].x, acc[d][0].y, acc[d][1].x, acc[d][1].y);
        *(float4*)&g_A[b][kbase + r0 + d][jbase + c0 + 2] =
            make_float4(acc[d][2].x, acc[d][2].y, acc[d][3].x, acc[d][3].y);
    }
}

// snapshot of column block kb
__global__ void k_copycol(int kb) {
    int idx = blockIdx.x * 256 + threadIdx.x;        // B*N*64 total
    int c = idx & 63, i = (idx >> 6) & (Nn - 1), b = idx >> 16;
    g_F[b][i][c] = g_A[b][i][kb*NB + c];
}

// trailing update: A[i, j] = (j==kcol ? 0 : A[i,j]) - F[i,:] @ A[k, j]   for i-block != kb
__global__ __launch_bounds__(256) void k_update(int kb) {
    int jt = blockIdx.x, it = blockIdx.y, b = blockIdx.z;
    if (it == kb) return;
    __shared__ __align__(16) float2 Ls[64][64];
    __shared__ __align__(16) float2 Rs[64][64];
    int t = threadIdx.x;
    int ibase = it * NB, jbase = jt * NB, kbase = kb * NB;
#pragma unroll
    for (int s = 0; s < 16; s++) {
        int e = t + 256*s; int r = e >> 6, c = e & 63;
        Ls[r][c] = g_F[b][ibase + r][c];
        Rs[r][c] = g_A[b][kbase + r][jbase + c];
    }
    __syncthreads();
    int tx = t & 15, ty = t >> 4, r0 = ty*4, c0 = tx*4;
    float2 acc[4][4];
    if (jt == kb) {
#pragma unroll
        for (int d = 0; d < 4; d++)
#pragma unroll
            for (int e2 = 0; e2 < 4; e2++) acc[d][e2] = make_float2(0.f, 0.f);
    } else {
#pragma unroll
        for (int d = 0; d < 4; d++) {
            float4 v0 = *(const float4*)&g_A[b][ibase + r0 + d][jbase + c0];
            float4 v1 = *(const float4*)&g_A[b][ibase + r0 + d][jbase + c0 + 2];
            acc[d][0] = make_float2(v0.x, v0.y); acc[d][1] = make_float2(v0.z, v0.w);
            acc[d][2] = make_float2(v1.x, v1.y); acc[d][3] = make_float2(v1.z, v1.w);
        }
    }
    tile_cgemm<true>(Ls, Rs, acc, r0, c0);
#pragma unroll
    for (int d = 0; d < 4; d++) {
        *(float4*)&g_A[b][ibase + r0 + d][jbase + c0]     =
            make_float4(acc[d][0].x, acc[d][0].y, acc[d][1].x, acc[d][1].y);
        *(float4*)&g_A[b][ibase + r0 + d][jbase + c0 + 2] =
            make_float4(acc[d][2].x, acc[d][2].y, acc[d][3].x, acc[d][3].y);
    }
}

// propagator = |A^{-1}| elementwise
__global__ void k_abs(float* __restrict__ out) {
    int idx = blockIdx.x * 256 + threadIdx.x;        // 4 complex per thread
    const float4* A4 = (const float4*)g_A;
    float4 u0 = A4[idx*2], u1 = A4[idx*2 + 1];
    float4 o;
    float s0 = u0.x*u0.x + u0.y*u0.y; o.x = s0 > 0.f ? s0 * rsqrtf(s0) : 0.f;
    float s1 = u0.z*u0.z + u0.w*u0.w; o.y = s1 > 0.f ? s1 * rsqrtf(s1) : 0.f;
    float s2 = u1.x*u1.x + u1.y*u1.y; o.z = s2 > 0.f ? s2 * rsqrtf(s2) : 0.f;
    float s3 = u1.z*u1.z + u1.w*u1.w; o.w = s3 > 0.f ? s3 * rsqrtf(s3) : 0.f;
    ((float4*)(out + PROP_OFF))[idx] = o;
}

// ---------------- launch ----------------
extern "C" void kernel_launch(void* const* d_in, const int* in_sizes, int n_in,
                              void* d_out, int out_size) {
    const float* gene = (const float*)d_in[0];
    const float* coh  = (const float*)d_in[1];
    const float* emb  = (const float*)d_in[2];
    const float* gb   = (const float*)d_in[3];
    const float* ew1  = (const float*)d_in[4];
    const float* eb1  = (const float*)d_in[5];
    const float* ew2  = (const float*)d_in[6];
    const float* eb2  = (const float*)d_in[7];
    const float* ow1  = (const float*)d_in[8];
    const float* ob1  = (const float*)d_in[9];
    const float* ow2  = (const float*)d_in[10];
    const float* ob2  = (const float*)d_in[11];
    const float* Hm   = (const float*)d_in[12];
    float* out = (float*)d_out;

    k_cell<<<Bz, 256>>>(gene);
    k_mlp<<<(Bz*Nn)/8, 256>>>(gene, coh, gb, ew1, eb1, ew2, eb2, ow1, ob1, ow2, ob2, out);
    k_probs<<<1, 32>>>(emb, out);
    k_omred<<<Bz, 256>>>();
    k_sym<<<dim3(32, 32), dim3(32, 8)>>>(Hm);
    k_build<<<dim3(Nn, Bz), 256>>>();

    for (int kb = 0; kb < NT; kb++) {
        k_diag<<<Bz, 256>>>(kb);
        k_rowscale<<<dim3(NT, Bz), 256>>>(kb);
        k_copycol<<<(Bz*Nn*NB)/256, 256>>>(kb);
        k_update<<<dim3(NT, NT, Bz), 256>>>(kb);
    }
    k_abs<<<(Bz*Nn*Nn)/(256*4), 256>>>(out);
}

// round 7
// speedup vs baseline: 1.0130x; 1.0130x over previous
#include <cuda_runtime.h>
#include <math.h>

// ---------------- problem constants ----------------
#define Bz   16
#define Nn   1024
#define Hh   64
#define NB   64
#define NT   16          // Nn / NB
#define ETA_ 0.01f

// output layout (tuple order, flattened)
#define SP_OFF    0
#define DEC_OFF   32
#define GAMMA_OFF (32 + Bz*Nn*Hh)            // 1048608
#define PROP_OFF  (GAMMA_OFF + Bz*Nn)        // 1064992

// ---------------- device scratch (static, no runtime alloc) ----------------
__device__ __align__(16) float2 g_A[Bz][Nn][Nn];   // working matrices -> inverses (134 MB)
__device__ __align__(16) float2 g_F[Bz][Nn][NB];   // NEGATED column-block snapshot (8.4 MB)
__device__ float g_Hs[Nn][Nn];                     // 0.5*(H+H^T) (4 MB)
__device__ float g_cell[Bz][Hh];
__device__ float g_omega[Bz][Nn];
__device__ float g_wre[Bz];

// ---------------- packed f32x2 helpers (Blackwell FFMA2) ----------------
__device__ __forceinline__ unsigned long long pack2(float x, float y) {
    unsigned long long r;
    asm("mov.b64 %0, {%1, %2};" : "=l"(r) : "f"(x), "f"(y));
    return r;
}
__device__ __forceinline__ void unpack2(unsigned long long v, float& x, float& y) {
    asm("mov.b64 {%0, %1}, %2;" : "=f"(x), "=f"(y) : "l"(v));
}
__device__ __forceinline__ void ffma2(unsigned long long& d,
                                      unsigned long long a, unsigned long long b) {
    asm("fma.rn.f32x2 %0, %1, %2, %0;" : "+l"(d) : "l"(a), "l"(b));
}

// ---------------- 64x64x64 complex tile GEMM core (packed) ----------------
// a1[d][c] += sum_k (ax,ax)*(bre,bim) ; a2[d][c] += sum_k (ay,ay)*(bre,bim)
// final complex value = (a1.lo - a2.hi, a1.hi + a2.lo)
__device__ __forceinline__ void cgemm2_body(const float2 (*Ls)[64],
                                            const unsigned long long (*Rs)[64],
                                            unsigned long long (*a1)[4],
                                            unsigned long long (*a2)[4],
                                            int r0, int c0) {
#pragma unroll 4
    for (int kk = 0; kk < 64; kk++) {
        unsigned long long axx[4], ayy[4];
#pragma unroll
        for (int d = 0; d < 4; d++) {
            float2 a = Ls[r0 + d][kk];
            axx[d] = pack2(a.x, a.x);
            ayy[d] = pack2(a.y, a.y);
        }
        ulonglong2 b01 = *(const ulonglong2*)&Rs[kk][c0];
        ulonglong2 b23 = *(const ulonglong2*)&Rs[kk][c0 + 2];
        unsigned long long b0 = b01.x, b1 = b01.y, b2 = b23.x, b3 = b23.y;
#pragma unroll
        for (int d = 0; d < 4; d++) {
            ffma2(a1[d][0], axx[d], b0); ffma2(a2[d][0], ayy[d], b0);
            ffma2(a1[d][1], axx[d], b1); ffma2(a2[d][1], ayy[d], b1);
            ffma2(a1[d][2], axx[d], b2); ffma2(a2[d][2], ayy[d], b2);
            ffma2(a1[d][3], axx[d], b3); ffma2(a2[d][3], ayy[d], b3);
        }
    }
}

// combine + store 4x4 tile to g_A
__device__ __forceinline__ void cgemm2_store(unsigned long long (*a1)[4],
                                             unsigned long long (*a2)[4],
                                             float2* rowbase0, int rowstride_f2,
                                             int c0) {
#pragma unroll
    for (int d = 0; d < 4; d++) {
        float x0, y0, x1, y1, x2, y2, x3, y3;
        float p0, q0, p1, q1, p2, q2, p3, q3;
        unpack2(a1[d][0], x0, y0); unpack2(a2[d][0], p0, q0);
        unpack2(a1[d][1], x1, y1); unpack2(a2[d][1], p1, q1);
        unpack2(a1[d][2], x2, y2); unpack2(a2[d][2], p2, q2);
        unpack2(a1[d][3], x3, y3); unpack2(a2[d][3], p3, q3);
        float2* row = rowbase0 + (size_t)d * rowstride_f2 + c0;
        *(float4*)&row[0] = make_float4(x0 - q0, y0 + p0, x1 - q1, y1 + p1);
        *(float4*)&row[2] = make_float4(x2 - q2, y2 + p2, x3 - q3, y3 + p3);
    }
}

// ---------------- small/fused kernels ----------------

__global__ void k_cell(const float* __restrict__ gene) {
    __shared__ float part[256];
    int b = blockIdx.x, t = threadIdx.x;
    int h = t & 63, chunk = t >> 6;
    const float* base = gene + ((size_t)b*Nn + chunk*256)*Hh + h;
    float s = 0.f;
    for (int n = 0; n < 256; n++) s += base[(size_t)n*Hh];
    part[t] = s;
    __syncthreads();
    if (t < 64)
        g_cell[b][t] = (part[t] + part[t+64] + part[t+128] + part[t+192]) * (1.0f/1024.0f);
}

__global__ __launch_bounds__(256) void k_mlp(
    const float* __restrict__ gene, const float* __restrict__ coh,
    const float* __restrict__ gb,
    const float* __restrict__ ew1, const float* __restrict__ eb1,
    const float* __restrict__ ew2, const float* __restrict__ eb2,
    const float* __restrict__ ow1, const float* __restrict__ ob1,
    const float* __restrict__ ow2, const float* __restrict__ ob2,
    float* __restrict__ out)
{
    __shared__ float swe[64][32], swo[64][32];
    __shared__ float sg[8][64];
    __shared__ float sw2e[32], sw2o[32];
    int t = threadIdx.x;
#pragma unroll
    for (int s = 0; s < 8; s++) {
        int e = t + 256*s;
        swe[e>>5][e&31] = ew1[e];
        swo[e>>5][e&31] = ow1[e];
    }
    if (t < 32) { sw2e[t] = ew2[t]; sw2o[t] = ow2[t]; }
    __syncthreads();

    int w = t >> 5, lane = t & 31;
    int row = blockIdx.x * 8 + w;           // b*N + n
    int b = row >> 10, n = row & (Nn-1);

    const float* grow = gene + (size_t)row*Hh;
    sg[w][lane]    = grow[lane];
    sg[w][lane+32] = grow[lane+32];
    __syncwarp();

    float ae = eb1[lane], ao = ob1[lane];
#pragma unroll
    for (int h = 0; h < 64; h++) {
        float g = sg[w][h];
        ae = fmaf(g, swe[h][lane], ae);
        ao = fmaf(g, swo[h][lane], ao);
    }
    float h1 = ae / (1.0f + expf(-ae));   // silu
    float o1 = ao / (1.0f + expf(-ao));
    float ve = h1 * sw2e[lane];
    float vo = o1 * sw2o[lane];
    float cs = sg[w][lane] + sg[w][lane+32];
#pragma unroll
    for (int off = 16; off; off >>= 1) {
        ve += __shfl_xor_sync(0xffffffffu, ve, off);
        vo += __shfl_xor_sync(0xffffffffu, vo, off);
        cs += __shfl_xor_sync(0xffffffffu, cs, off);
    }
    float env   = 1.0f / (1.0f + expf(-(ve + eb2[0])));
    float omega = vo + ob2[0];
    float gamma = (1.0f / (1.0f + expf(-gb[n]))) * (1.0f + env);
    float classical = cs * (1.0f/64.0f);

    if (lane == 0) {
        out[GAMMA_OFF + row] = gamma;
        g_omega[b][n] = omega;
    }
    float om1 = 1.0f - gamma;
    const float* crow = coh + (size_t)row*Hh;
    float* drow = out + DEC_OFF + (size_t)row*Hh;
    drow[lane]    = om1*crow[lane]    + gamma*classical;
    drow[lane+32] = om1*crow[lane+32] + gamma*classical;
}

__global__ void k_omred() {
    __shared__ float s[256];
    int b = blockIdx.x, t = threadIdx.x;
    s[t] = g_omega[b][t] + g_omega[b][t+256] + g_omega[b][t+512] + g_omega[b][t+768];
    __syncthreads();
    for (int off = 128; off; off >>= 1) { if (t < off) s[t] += s[t+off]; __syncthreads(); }
    if (t == 0) g_wre[b] = s[0] * (1.0f/1024.0f);
}

__global__ void k_probs(const float* __restrict__ emb, float* __restrict__ out) {
    int t = threadIdx.x;
    if (t >= 16) return;
    float nc = 0.f, d0 = 0.f, d1 = 0.f, n0 = 0.f, n1 = 0.f;
    for (int d = 0; d < 64; d++) {
        float c = g_cell[t][d];
        float e0 = emb[d], e1 = emb[64 + d];
        nc = fmaf(c, c, nc); d0 = fmaf(c, e0, d0); d1 = fmaf(c, e1, d1);
        n0 = fmaf(e0, e0, n0); n1 = fmaf(e1, e1, n1);
    }
    float ic = 1.0f / fmaxf(sqrtf(nc), 1e-12f);
    float l0 = d0 * ic / fmaxf(sqrtf(n0), 1e-12f) * 10.0f;
    float l1 = d1 * ic / fmaxf(sqrtf(n1), 1e-12f) * 10.0f;
    float m = fmaxf(l0, l1);
    float p0 = expf(l0 - m), p1 = expf(l1 - m);
    float is = 1.0f / (p0 + p1);
    out[SP_OFF + t*2 + 0] = p0 * is;
    out[SP_OFF + t*2 + 1] = p1 * is;
}

__global__ void k_sym(const float* __restrict__ Hm) {
    __shared__ float tile[32][33];
    int bx = blockIdx.x, by = blockIdx.y;
    int tx = threadIdx.x, ty = threadIdx.y;
#pragma unroll
    for (int s = 0; s < 32; s += 8)
        tile[ty+s][tx] = Hm[(size_t)(bx*32 + ty + s)*Nn + by*32 + tx];
    __syncthreads();
#pragma unroll
    for (int s = 0; s < 32; s += 8) {
        int i = by*32 + ty + s, j = bx*32 + tx;
        g_Hs[i][j] = 0.5f * (Hm[(size_t)i*Nn + j] + tile[tx][ty+s]);
    }
}

__global__ void k_build() {
    int i = blockIdx.x, b = blockIdx.y, t = threadIdx.x;
    float wre = g_wre[b];
#pragma unroll
    for (int s = 0; s < 4; s++) {
        int j = t + 256*s;
        float re = ((i == j) ? wre : 0.0f) - g_Hs[i][j];
        g_A[b][i][j] = make_float2(re, (i == j) ? ETA_ : 0.0f);
    }
}

// ---------------- blocked Gauss-Jordan (no pivoting; Im = eta*I guarantees pivots) ----------------

// invert 64x64 diagonal block in place (scalar fp32; tiny fraction of runtime)
__global__ __launch_bounds__(256) void k_diag(int kb) {
    __shared__ float2 M[64][64];
    int b = blockIdx.x, t = threadIdx.x;
    int kbase = kb * NB;
#pragma unroll
    for (int s = 0; s < 16; s++) {
        int e = t + 256*s; int r = e >> 6, c = e & 63;
        M[r][c] = g_A[b][kbase + r][kbase + c];
    }
    __syncthreads();
    int jj = t & 63, i0 = t >> 6;
    for (int k = 0; k < 64; k++) {
        float2 p = M[k][k];
        float id = 1.0f / (p.x*p.x + p.y*p.y);
        float2 pinv = make_float2(p.x*id, -p.y*id);
        float2 rk = M[k][jj];
        float2 f[16];
#pragma unroll
        for (int m = 0; m < 16; m++) f[m] = M[i0 + 4*m][k];
        __syncthreads();
        float2 nrk;
        if (jj == k) nrk = pinv;
        else nrk = make_float2(rk.x*pinv.x - rk.y*pinv.y, rk.x*pinv.y + rk.y*pinv.x);
#pragma unroll
        for (int m = 0; m < 16; m++) {
            int i = i0 + 4*m;
            if (i == k) {
                M[k][jj] = nrk;
            } else if (jj == k) {
                M[i][k] = make_float2(-(f[m].x*pinv.x - f[m].y*pinv.y),
                                      -(f[m].x*pinv.y + f[m].y*pinv.x));
            } else {
                float2 v = M[i][jj];
                v.x -= f[m].x*nrk.x - f[m].y*nrk.y;
                v.y -= f[m].x*nrk.y + f[m].y*nrk.x;
                M[i][jj] = v;
            }
        }
        __syncthreads();
    }
#pragma unroll
    for (int s = 0; s < 16; s++) {
        int e = t + 256*s; int r = e >> 6, c = e & 63;
        g_A[b][kbase + r][kbase + c] = M[r][c];
    }
}

// row-block scale: A[k, jt] <- P @ A[k, jt]   (jt != kb), packed FFMA2 path
__global__ __launch_bounds__(256, 2) void k_rowscale(int kb) {
    int jt = blockIdx.x, b = blockIdx.y;
    if (jt == kb) return;
    __shared__ __align__(16) float2 Ls[64][64];
    __shared__ __align__(16) unsigned long long Rs[64][64];
    int t = threadIdx.x;
    int kbase = kb * NB, jbase = jt * NB;
#pragma unroll
    for (int s = 0; s < 16; s++) {
        int e = t + 256*s; int r = e >> 6, c = e & 63;
        Ls[r][c] = g_A[b][kbase + r][kbase + c];   // P
        Rs[r][c] = *(const unsigned long long*)&g_A[b][kbase + r][jbase + c];
    }
    __syncthreads();
    int tx = t & 15, ty = t >> 4, r0 = ty*4, c0 = tx*4;
    unsigned long long a1[4][4], a2[4][4];
#pragma unroll
    for (int d = 0; d < 4; d++)
#pragma unroll
        for (int c = 0; c < 4; c++) { a1[d][c] = 0ULL; a2[d][c] = 0ULL; }
    cgemm2_body(Ls, Rs, a1, a2, r0, c0);
    cgemm2_store(a1, a2, &g_A[b][kbase + r0][jbase], Nn, c0);
}

// negated snapshot of column block kb:  g_F = -A[:, kb]
__global__ void k_copycol(int kb) {
    int idx = blockIdx.x * 256 + threadIdx.x;        // B*N*64 total
    int c = idx & 63, i = (idx >> 6) & (Nn - 1), b = idx >> 16;
    float2 v = g_A[b][i][kb*NB + c];
    g_F[b][i][c] = make_float2(-v.x, -v.y);
}

// trailing update: A[i,j] = (j==kb ? 0 : A[i,j]) + (-F)[i,:] @ A[k,j]   for i-block != kb
__global__ __launch_bounds__(256, 2) void k_update(int kb) {
    int jt = blockIdx.x, it = blockIdx.y, b = blockIdx.z;
    if (it == kb) return;
    __shared__ __align__(16) float2 Ls[64][64];
    __shared__ __align__(16) unsigned long long Rs[64][64];
    int t = threadIdx.x;
    int ibase = it * NB, jbase = jt * NB, kbase = kb * NB;
#pragma unroll
    for (int s = 0; s < 16; s++) {
        int e = t + 256*s; int r = e >> 6, c = e & 63;
        Ls[r][c] = g_F[b][ibase + r][c];                                     // -F
        Rs[r][c] = *(const unsigned long long*)&g_A[b][kbase + r][jbase + c];
    }
    __syncthreads();
    int tx = t & 15, ty = t >> 4, r0 = ty*4, c0 = tx*4;
    unsigned long long a1[4][4], a2[4][4];
    if (jt == kb) {
#pragma unroll
        for (int d = 0; d < 4; d++)
#pragma unroll
            for (int c = 0; c < 4; c++) a1[d][c] = 0ULL;
    } else {
#pragma unroll
        for (int d = 0; d < 4; d++) {
            ulonglong2 v0 = *(const ulonglong2*)&g_A[b][ibase + r0 + d][jbase + c0];
            ulonglong2 v1 = *(const ulonglong2*)&g_A[b][ibase + r0 + d][jbase + c0 + 2];
            a1[d][0] = v0.x; a1[d][1] = v0.y; a1[d][2] = v1.x; a1[d][3] = v1.y;
        }
    }
#pragma unroll
    for (int d = 0; d < 4; d++)
#pragma unroll
        for (int c = 0; c < 4; c++) a2[d][c] = 0ULL;
    cgemm2_body(Ls, Rs, a1, a2, r0, c0);
    cgemm2_store(a1, a2, &g_A[b][ibase + r0][jbase], Nn, c0);
}

// propagator = |A^{-1}| elementwise
__global__ void k_abs(float* __restrict__ out) {
    int idx = blockIdx.x * 256 + threadIdx.x;        // 4 complex per thread
    const float4* A4 = (const float4*)g_A;
    float4 u0 = A4[idx*2], u1 = A4[idx*2 + 1];
    float4 o;
    float s0 = u0.x*u0.x + u0.y*u0.y; o.x = s0 > 0.f ? s0 * rsqrtf(s0) : 0.f;
    float s1 = u0.z*u0.z + u0.w*u0.w; o.y = s1 > 0.f ? s1 * rsqrtf(s1) : 0.f;
    float s2 = u1.x*u1.x + u1.y*u1.y; o.z = s2 > 0.f ? s2 * rsqrtf(s2) : 0.f;
    float s3 = u1.z*u1.z + u1.w*u1.w; o.w = s3 > 0.f ? s3 * rsqrtf(s3) : 0.f;
    ((float4*)(out + PROP_OFF))[idx] = o;
}

// ---------------- launch ----------------
extern "C" void kernel_launch(void* const* d_in, const int* in_sizes, int n_in,
                              void* d_out, int out_size) {
    const float* gene = (const float*)d_in[0];
    const float* coh  = (const float*)d_in[1];
    const float* emb  = (const float*)d_in[2];
    const float* gb   = (const float*)d_in[3];
    const float* ew1  = (const float*)d_in[4];
    const float* eb1  = (const float*)d_in[5];
    const float* ew2  = (const float*)d_in[6];
    const float* eb2  = (const float*)d_in[7];
    const float* ow1  = (const float*)d_in[8];
    const float* ob1  = (const float*)d_in[9];
    const float* ow2  = (const float*)d_in[10];
    const float* ob2  = (const float*)d_in[11];
    const float* Hm   = (const float*)d_in[12];
    float* out = (float*)d_out;

    k_cell<<<Bz, 256>>>(gene);
    k_mlp<<<(Bz*Nn)/8, 256>>>(gene, coh, gb, ew1, eb1, ew2, eb2, ow1, ob1, ow2, ob2, out);
    k_probs<<<1, 32>>>(emb, out);
    k_omred<<<Bz, 256>>>();
    k_sym<<<dim3(32, 32), dim3(32, 8)>>>(Hm);
    k_build<<<dim3(Nn, Bz), 256>>>();

    for (int kb = 0; kb < NT; kb++) {
        k_diag<<<Bz, 256>>>(kb);
        k_rowscale<<<dim3(NT, Bz), 256>>>(kb);
        k_copycol<<<(Bz*Nn*NB)/256, 256>>>(kb);
        k_update<<<dim3(NT, NT, Bz), 256>>>(kb);
    }
    k_abs<<<(Bz*Nn*Nn)/(256*4), 256>>>(out);
}